// round 15
// baseline (speedup 1.0000x reference)
#include <cuda_runtime.h>
#include <cuda_bf16.h>
#include <mma.h>
#include <math.h>
#include <stdint.h>

using namespace nvcuda;

#define B_   2
#define S_   2048
#define D_   1024
#define H_   16
#define DK_  64
#define M_   16
#define L_   4
#define DFF_ 4096
#define VT_  69
#define VS_  69
#define FD_  34
#define BS_  (B_*S_)
#define QS2_ 1536            // packed [qfeat 256 | kfeat 256 | v 1024]
#define VOFF 512
#define CCH  64
#define TCH  32
#define EPSF 1e-6f

#define DD_       ((size_t)D_*D_)
#define R_QKV     ((size_t)QS2_*D_)
#define OFF_QKV   ((size_t)0)
#define OFF_WO    ((size_t)L_*R_QKV)
#define OFF_FF1   (OFF_WO  + (size_t)L_*DD_)
#define OFF_FF2   (OFF_FF1 + (size_t)L_*4*DD_)
#define OFF_PROJ  (OFF_FF2 + (size_t)L_*4*DD_)
#define WTOT      (OFF_PROJ + (size_t)VT_*D_)

// ---------------- scratch ----------------------------------------------------
__device__ __align__(16) float g_emb2[VS_*D_];
__device__ __align__(16) float g_x   [BS_*D_];
__device__ __align__(16) __nv_bfloat16 g_xh[BS_*D_];
__device__ __align__(16) __nv_bfloat16 g_xl[BS_*D_];
__device__ __align__(16) float g_qkv [(size_t)BS_*QS2_];
__device__ __align__(16) __nv_bfloat16 g_ah[BS_*D_];
__device__ __align__(16) __nv_bfloat16 g_al[BS_*D_];
__device__ __align__(16) __nv_bfloat16 g_h1h[(size_t)BS_*DFF_];
__device__ __align__(16) __nv_bfloat16 g_h1l[(size_t)BS_*DFF_];
__device__ __align__(16) __nv_bfloat16 g_wh[WTOT];
__device__ __align__(16) __nv_bfloat16 g_wl[WTOT];
__device__ __align__(16) float g_ckv[(size_t)B_*H_*CCH*M_*DK_];
__device__ __align__(16) float g_ck [B_*H_*CCH*M_];
__device__ float g_gate[B_*H_];

// ---------------- helpers -----------------------------------------------------
static __device__ __forceinline__ uint32_t pack_hi(float a, float b, uint32_t& lo)
{
    __nv_bfloat16 ha = __float2bfloat16(a), hb = __float2bfloat16(b);
    __nv_bfloat162 h = __halves2bfloat162(ha, hb);
    __nv_bfloat162 l = __halves2bfloat162(__float2bfloat16(a - __bfloat162float(ha)),
                                          __float2bfloat16(b - __bfloat162float(hb)));
    lo = *(uint32_t*)&l;
    return *(uint32_t*)&h;
}

static __device__ __forceinline__ float fgelu(float x)
{
    float u = 0.7978845608028654f*(x + 0.044715f*x*x*x);
    float e = __expf(2.f*u);                // tanh(u) = 1 - 2/(e^{2u}+1)
    float t = 1.f - 2.f/(e + 1.f);
    return 0.5f*x*(1.f + t);
}

// ---------------- weight split: 8 floats/thread, 16B coalesced stores --------
__global__ void wsplit_kernel(const float4* __restrict__ src, size_t n16, size_t dstOff)
{
    uint4* wh4 = (uint4*)(g_wh + dstOff);
    uint4* wl4 = (uint4*)(g_wl + dstOff);
    for (size_t i = (size_t)blockIdx.x*blockDim.x + threadIdx.x; i < n16;
         i += (size_t)gridDim.x*blockDim.x) {
        float4 v0 = src[i*2];
        float4 v1 = src[i*2 + 1];
        uint4 uh, ul;
        uh.x = pack_hi(v0.x, v0.y, ul.x);
        uh.y = pack_hi(v0.z, v0.w, ul.y);
        uh.z = pack_hi(v1.x, v1.y, ul.z);
        uh.w = pack_hi(v1.z, v1.w, ul.w);
        wh4[i] = uh;
        wl4[i] = ul;
    }
}

// v-panels for all layers in one launch (blockIdx.y = layer)
__global__ void wsplitv_kernel(const float4* __restrict__ wv)
{
    int l = blockIdx.y;
    const float4* src = wv + (size_t)l*DD_/4;
    size_t dstOff = OFF_QKV + (size_t)l*R_QKV + (size_t)VOFF*D_;
    uint4* wh4 = (uint4*)(g_wh + dstOff);
    uint4* wl4 = (uint4*)(g_wl + dstOff);
    size_t n16 = DD_/8;
    for (size_t i = (size_t)blockIdx.x*blockDim.x + threadIdx.x; i < n16;
         i += (size_t)gridDim.x*blockDim.x) {
        float4 v0 = src[i*2];
        float4 v1 = src[i*2 + 1];
        uint4 uh, ul;
        uh.x = pack_hi(v0.x, v0.y, ul.x);
        uh.y = pack_hi(v0.z, v0.w, ul.y);
        uh.z = pack_hi(v1.x, v1.y, ul.z);
        uh.w = pack_hi(v1.z, v1.w, ul.w);
        wh4[i] = uh;
        wl4[i] = ul;
    }
}

// ---------------- fold omega into wq/wk — all layers, one launch --------------
// blockIdx.z = l*2 + (0:q, 1:k)
__global__ void __launch_bounds__(256) featfold_kernel(
    const float* __restrict__ wq, const float* __restrict__ wk,
    const float* __restrict__ omega)
{
    int z = blockIdx.z;
    int l = z >> 1;
    int isK = z & 1;
    const float* w = (isK ? wk : wq) + (size_t)l*DD_;
    const float* om = omega + (size_t)l*M_*DK_;
    size_t dstRowBase = OFF_QKV + (size_t)l*R_QKV + (isK ? (size_t)256*D_ : 0);
    int h = blockIdx.y;
    int dl = threadIdx.x & 127;
    int seg = threadIdx.x >> 7;
    int d = blockIdx.x*128 + dl;
    __shared__ float so[M_][DK_];
    __shared__ float red[128][M_];
    for (int i = threadIdx.x; i < M_*DK_; i += 256) so[i/DK_][i%DK_] = om[i];
    __syncthreads();
    float acc[M_];
    #pragma unroll
    for (int m = 0; m < M_; m++) acc[m] = 0.f;
    const float* wp = w + (size_t)(h*DK_ + seg*32)*D_ + d;
    #pragma unroll 8
    for (int dk = 0; dk < 32; dk++) {
        float wv = wp[(size_t)dk*D_];
        #pragma unroll
        for (int m = 0; m < M_; m++) acc[m] += so[m][seg*32 + dk]*wv;
    }
    if (seg == 1) {
        #pragma unroll
        for (int m = 0; m < M_; m++) red[dl][m] = acc[m];
    }
    __syncthreads();
    if (seg == 0) {
        #pragma unroll
        for (int m = 0; m < M_; m++) {
            float v = acc[m] + red[dl][m];
            __nv_bfloat16 hh = __float2bfloat16(v);
            size_t oi = dstRowBase + (size_t)(h*M_+m)*D_ + d;
            g_wh[oi] = hh;
            g_wl[oi] = __float2bfloat16(v - __bfloat162float(hh));
        }
    }
}

// ---------------- embedding / init / gate ------------------------------------
__global__ void embtbl_kernel(const float* __restrict__ id_embed,
                              const float* __restrict__ feat_proj,
                              const float* __restrict__ gammap,
                              const float* __restrict__ feat_tbl)
{
    int v = blockIdx.x;
    float gscale = gammap[0] * ((v >= 10) ? 1.f : 0.f);
    __shared__ float ft[FD_];
    if (threadIdx.x < FD_) ft[threadIdx.x] = feat_tbl[v*FD_ + threadIdx.x];
    __syncthreads();
    for (int d = threadIdx.x; d < D_; d += blockDim.x) {
        float dot = 0.f;
        #pragma unroll
        for (int f = 0; f < FD_; f++) dot += ft[f] * feat_proj[d*FD_ + f];
        g_emb2[v*D_ + d] = id_embed[(size_t)v*D_ + d] + gscale * dot;
    }
}

__global__ void xinit_kernel(const int* __restrict__ ids, const float* __restrict__ pe)
{
    int idx = blockIdx.x*blockDim.x + threadIdx.x;
    if (idx >= BS_*D_) return;
    int d = idx % D_;
    int bs = idx / D_;
    int s = bs % S_;
    g_x[idx] = g_emb2[ids[bs]*D_ + d] + pe[(size_t)s*D_ + d];
}

__global__ void gate_kernel(const int* __restrict__ user_ids,
                            const float* __restrict__ gl)
{
    int b = blockIdx.x;
    int lane = threadIdx.x;
    float v = (lane < H_) ? gl[(size_t)user_ids[b]*H_ + lane] : -1e30f;
    float mx = v;
    #pragma unroll
    for (int o = 16; o > 0; o >>= 1) mx = fmaxf(mx, __shfl_xor_sync(~0u, mx, o));
    float e = (lane < H_) ? expf(v - mx) : 0.f;
    float s = e;
    #pragma unroll
    for (int o = 16; o > 0; o >>= 1) s += __shfl_xor_sync(~0u, s, o);
    if (lane < H_) g_gate[b*H_ + lane] = e / s;
}

// ---------------- LayerNorm -> bf16 hi/lo (vectorized) ------------------------
__global__ void __launch_bounds__(256) ln_kernel(const float* __restrict__ X,
                                                 const float* __restrict__ alpha,
                                                 const float* __restrict__ beta,
                                                 __nv_bfloat16* __restrict__ Yh,
                                                 __nv_bfloat16* __restrict__ Yl)
{
    int row = blockIdx.x;
    int tid = threadIdx.x;
    const float4* x4 = (const float4*)(X + (size_t)row*D_);
    float4 v = x4[tid];
    float s  = v.x + v.y + v.z + v.w;
    float s2 = v.x*v.x + v.y*v.y + v.z*v.z + v.w*v.w;

    __shared__ float red[64];
    #pragma unroll
    for (int o = 16; o > 0; o >>= 1) {
        s  += __shfl_down_sync(~0u, s,  o);
        s2 += __shfl_down_sync(~0u, s2, o);
    }
    int w = tid >> 5, lane = tid & 31;
    if (lane == 0) { red[w] = s; red[w+32] = s2; }
    __syncthreads();
    if (w == 0) {
        s  = (lane < 8) ? red[lane]    : 0.f;
        s2 = (lane < 8) ? red[lane+32] : 0.f;
        #pragma unroll
        for (int o = 4; o > 0; o >>= 1) {
            s  += __shfl_down_sync(~0u, s,  o);
            s2 += __shfl_down_sync(~0u, s2, o);
        }
        if (lane == 0) { red[0] = s; red[1] = s2; }
    }
    __syncthreads();
    float mu  = red[0] / (float)D_;
    float var = (red[1] - (float)D_*mu*mu) / (float)(D_-1);
    float inv = 1.f / (sqrtf(fmaxf(var, 0.f)) + EPSF);

    float4 a4 = ((const float4*)alpha)[tid];
    float4 b4 = ((const float4*)beta)[tid];
    float o0 = a4.x*(v.x - mu)*inv + b4.x;
    float o1 = a4.y*(v.y - mu)*inv + b4.y;
    float o2 = a4.z*(v.z - mu)*inv + b4.z;
    float o3 = a4.w*(v.w - mu)*inv + b4.w;

    uint2 uh, ul;
    uh.x = pack_hi(o0, o1, ul.x);
    uh.y = pack_hi(o2, o3, ul.y);
    ((uint2*)(Yh + (size_t)row*D_))[tid] = uh;
    ((uint2*)(Yl + (size_t)row*D_))[tid] = ul;
}

// =============================================================================
//  split-bf16 mma.sync GEMM primitives
// =============================================================================
#define ROWB 48
#define STG_BYTES 24576
#define TG4_SMEM  (4u*STG_BYTES)   // 98304

static __device__ __forceinline__ void cpa16s(uint32_t dst, const void* src) {
    asm volatile("cp.async.cg.shared.global [%0], [%1], 16;" :: "r"(dst), "l"(src));
}
static __device__ __forceinline__ void ldm4(uint32_t* d, uint32_t a) {
    asm volatile("ldmatrix.sync.aligned.m8n8.x4.shared.b16 {%0,%1,%2,%3}, [%4];"
                 : "=r"(d[0]), "=r"(d[1]), "=r"(d[2]), "=r"(d[3]) : "r"(a));
}
static __device__ __forceinline__ void mma16816(float* c, const uint32_t* a, const uint32_t* b) {
    asm volatile("mma.sync.aligned.m16n8k16.row.col.f32.bf16.bf16.f32 "
                 "{%0,%1,%2,%3},{%4,%5,%6,%7},{%8,%9},{%0,%1,%2,%3};"
                 : "+f"(c[0]), "+f"(c[1]), "+f"(c[2]), "+f"(c[3])
                 : "r"(a[0]), "r"(a[1]), "r"(a[2]), "r"(a[3]), "r"(b[0]), "r"(b[1]));
}

template<int EPI>
static __device__ __forceinline__ void epi_pair(
    float v0, float v1, int rr, int cc, size_t gi,
    const float* bias, const float* res,
    float* Cf, __nv_bfloat16* Ch, __nv_bfloat16* Cl)
{
    if (EPI == 2) {
        v0 = fgelu(v0 + bias[cc]);
        v1 = fgelu(v1 + bias[cc+1]);
        uint32_t lo;
        uint32_t hi = pack_hi(v0, v1, lo);
        *(uint32_t*)(Ch + gi) = hi;
        *(uint32_t*)(Cl + gi) = lo;
    } else {
        if (EPI == 3) { float2 r = *(const float2*)(res + gi); v0 += r.x; v1 += r.y; }
        if (EPI == 4) {
            float2 r = *(const float2*)(res + gi);
            v0 += bias[cc] + r.x; v1 += bias[cc+1] + r.y;
        }
        *(float2*)(Cf + gi) = make_float2(v0, v1);
    }
}

// shared per-chunk compute (128x128 tile, warp = 32x64)
static __device__ __forceinline__ void tg_compute(
    float acc[2][8][4], uint32_t bb, uint32_t aoff, uint32_t boff)
{
    uint32_t aH[2][4], aL[2][4];
    ldm4(aH[0], bb + aoff);
    ldm4(aH[1], bb + aoff + 16*ROWB);
    ldm4(aL[0], bb + 6144 + aoff);
    ldm4(aL[1], bb + 6144 + aoff + 16*ROWB);

    #pragma unroll
    for (int half = 0; half < 2; half++) {
        uint32_t bH[2][4], bL[2][4];
        uint32_t bo = boff + half*32*ROWB;
        ldm4(bH[0], bb + 12288 + bo);
        ldm4(bH[1], bb + 12288 + bo + 16*ROWB);
        ldm4(bL[0], bb + 18432 + bo);
        ldm4(bL[1], bb + 18432 + bo + 16*ROWB);
        #pragma unroll
        for (int t = 0; t < 4; t++) {
            int nj = half*4 + t;
            const uint32_t* bh = &bH[t >> 1][(t & 1)*2];
            const uint32_t* bl = &bL[t >> 1][(t & 1)*2];
            #pragma unroll
            for (int mi = 0; mi < 2; mi++) {
                mma16816(acc[mi][nj], aH[mi], bh);
                mma16816(acc[mi][nj], aL[mi], bh);
                mma16816(acc[mi][nj], aH[mi], bl);
            }
        }
    }
}

template<int EPI>
static __device__ __forceinline__ void tg_epilogue(
    float acc[2][8][4], int m0, int n0, int wm, int wn, int lane,
    const float* bias, const float* res,
    float* Cf, __nv_bfloat16* Ch, __nv_bfloat16* Cl, int Nc)
{
    const int gq = lane >> 2;
    const int qp = lane & 3;
    #pragma unroll
    for (int mi = 0; mi < 2; mi++) {
        #pragma unroll
        for (int nj = 0; nj < 8; nj++) {
            int r0 = m0 + wm*32 + mi*16 + gq;
            int cc = n0 + wn*64 + nj*8 + qp*2;
            #pragma unroll
            for (int hrow = 0; hrow < 2; hrow++) {
                int rr = r0 + hrow*8;
                epi_pair<EPI>(acc[mi][nj][hrow*2], acc[mi][nj][hrow*2+1],
                              rr, cc, (size_t)rr*Nc + cc, bias, res, Cf, Ch, Cl);
            }
        }
    }
}

// ---- 4-stage, single-sync-per-chunk, dynamic smem (proven optimum) ----------
template<int EPI>
__global__ void __launch_bounds__(256, 2) tgemm4(
    const __nv_bfloat16* __restrict__ Ah, const __nv_bfloat16* __restrict__ Al,
    const __nv_bfloat16* __restrict__ Bh, const __nv_bfloat16* __restrict__ Bl,
    const float* __restrict__ bias, const float* __restrict__ res,
    float* __restrict__ Cf, __nv_bfloat16* __restrict__ Ch, __nv_bfloat16* __restrict__ Cl,
    int Nc, int K)
{
    extern __shared__ __align__(16) unsigned char sm4[];
    const uint32_t smB = (uint32_t)__cvta_generic_to_shared(sm4);

    const int tid  = threadIdx.x;
    const int wid  = tid >> 5;
    const int lane = tid & 31;
    const int wm   = wid >> 1;
    const int wn   = wid & 1;
    const int m0 = blockIdx.y * 128;
    const int n0 = blockIdx.x * 128;

    float acc[2][8][4];
    #pragma unroll
    for (int i = 0; i < 2; i++)
        #pragma unroll
        for (int j = 0; j < 8; j++)
            #pragma unroll
            for (int q = 0; q < 4; q++) acc[i][j][q] = 0.f;

    const int crow = tid >> 1, cq = tid & 1;
    const uint32_t cdst = (uint32_t)(crow*ROWB + cq*16);
    const size_t  asrc = (size_t)(m0 + crow)*K + cq*8;
    const size_t  bsrc = (size_t)(n0 + crow)*K + cq*8;

    const uint32_t aoff = (uint32_t)((wm*32 + (lane & 15))*ROWB + (lane >> 4)*16);
    const uint32_t boff = (uint32_t)((wn*64 + ((lane >> 4) << 3) + (lane & 7))*ROWB
                                     + ((lane >> 3) & 1)*16);

    auto loadChunk = [&](int c, int buf) {
        uint32_t bb = smB + (uint32_t)buf*STG_BYTES + cdst;
        int k0 = c*16;
        cpa16s(bb,         Ah + asrc + k0);
        cpa16s(bb +  6144, Al + asrc + k0);
        cpa16s(bb + 12288, Bh + bsrc + k0);
        cpa16s(bb + 18432, Bl + bsrc + k0);
        asm volatile("cp.async.commit_group;");
    };

    const int nch = K >> 4;
    loadChunk(0, 0);
    loadChunk(1, 1);

    for (int c = 0; c < nch; c++) {
        if (c + 2 < nch) {
            loadChunk(c + 2, (c + 2) & 3);
            asm volatile("cp.async.wait_group 2;");
        } else if (c + 1 < nch) {
            asm volatile("cp.async.wait_group 1;");
        } else {
            asm volatile("cp.async.wait_group 0;");
        }
        __syncthreads();
        tg_compute(acc, smB + (uint32_t)(c & 3)*STG_BYTES, aoff, boff);
    }

    tg_epilogue<EPI>(acc, m0, n0, wm, wn, lane, bias, res, Cf, Ch, Cl, Nc);
}

// ---- 2-stage static-smem fallback (proven) ----------------------------------
template<int EPI>
__global__ void __launch_bounds__(256, 2) tgemm2(
    const __nv_bfloat16* __restrict__ Ah, const __nv_bfloat16* __restrict__ Al,
    const __nv_bfloat16* __restrict__ Bh, const __nv_bfloat16* __restrict__ Bl,
    const float* __restrict__ bias, const float* __restrict__ res,
    float* __restrict__ Cf, __nv_bfloat16* __restrict__ Ch, __nv_bfloat16* __restrict__ Cl,
    int Nc, int K)
{
    __shared__ __align__(16) unsigned char sm[2*STG_BYTES];
    const uint32_t smB = (uint32_t)__cvta_generic_to_shared(sm);

    const int tid  = threadIdx.x;
    const int wid  = tid >> 5;
    const int lane = tid & 31;
    const int wm   = wid >> 1;
    const int wn   = wid & 1;
    const int m0 = blockIdx.y * 128;
    const int n0 = blockIdx.x * 128;

    float acc[2][8][4];
    #pragma unroll
    for (int i = 0; i < 2; i++)
        #pragma unroll
        for (int j = 0; j < 8; j++)
            #pragma unroll
            for (int q = 0; q < 4; q++) acc[i][j][q] = 0.f;

    const int crow = tid >> 1, cq = tid & 1;
    const uint32_t cdst = (uint32_t)(crow*ROWB + cq*16);
    const size_t  asrc = (size_t)(m0 + crow)*K + cq*8;
    const size_t  bsrc = (size_t)(n0 + crow)*K + cq*8;

    const uint32_t aoff = (uint32_t)((wm*32 + (lane & 15))*ROWB + (lane >> 4)*16);
    const uint32_t boff = (uint32_t)((wn*64 + ((lane >> 4) << 3) + (lane & 7))*ROWB
                                     + ((lane >> 3) & 1)*16);

    auto loadChunk = [&](int c, int buf) {
        uint32_t bb = smB + (uint32_t)buf*STG_BYTES + cdst;
        int k0 = c*16;
        cpa16s(bb,         Ah + asrc + k0);
        cpa16s(bb +  6144, Al + asrc + k0);
        cpa16s(bb + 12288, Bh + bsrc + k0);
        cpa16s(bb + 18432, Bl + bsrc + k0);
        asm volatile("cp.async.commit_group;");
    };

    const int nch = K >> 4;
    loadChunk(0, 0);

    for (int c = 0; c < nch; c++) {
        if (c + 1 < nch) {
            loadChunk(c + 1, (c + 1) & 1);
            asm volatile("cp.async.wait_group 1;");
        } else {
            asm volatile("cp.async.wait_group 0;");
        }
        __syncthreads();
        tg_compute(acc, smB + (uint32_t)(c & 1)*STG_BYTES, aoff, boff);
        __syncthreads();
    }

    tg_epilogue<EPI>(acc, m0, n0, wm, wn, lane, bias, res, Cf, Ch, Cl, Nc);
}

// ---------------- wmma GEMM for the tiny VT=69 projection --------------------
__global__ void __launch_bounds__(256, 2) bgemm_proj(
    const __nv_bfloat16* __restrict__ Ah, const __nv_bfloat16* __restrict__ Al,
    const __nv_bfloat16* __restrict__ Bh, const __nv_bfloat16* __restrict__ Bl,
    const float* __restrict__ bias, float* __restrict__ Cf, int Nc, int K)
{
    __shared__ __align__(16) unsigned char smem_raw[49152];
    const int tid = threadIdx.x;
    const int warpId = tid >> 5;
    const int warp_m = warpId & 3;
    const int warp_n = warpId >> 2;
    const int m0 = blockIdx.y * 128;
    const int n0 = blockIdx.x * 128;

    wmma::fragment<wmma::accumulator,16,16,16,float> c[2][4];
    #pragma unroll
    for (int i = 0; i < 2; i++)
        #pragma unroll
        for (int j = 0; j < 4; j++) wmma::fill_fragment(c[i][j], 0.f);

    const int row  = tid >> 1;
    const int half = tid & 1;

    auto loadChunk = [&](int kc, int buf) {
        const int k0 = kc * 16;
        size_t aoff = (size_t)(m0 + row)*K + k0 + half*8;
        int brow = n0 + row;
        int bp = (brow < Nc) ? 16 : 0;
        size_t boff = (size_t)(bp ? brow : 0)*K + k0 + half*8;
        unsigned dst = (unsigned)__cvta_generic_to_shared(
            smem_raw + buf*24576 + (row*24 + half*8)*2);
        asm volatile("cp.async.cg.shared.global [%0], [%1], 16;\n" :: "r"(dst), "l"(Ah + aoff));
        asm volatile("cp.async.cg.shared.global [%0], [%1], 16;\n" :: "r"(dst + 6144), "l"(Al + aoff));
        asm volatile("cp.async.cg.shared.global [%0], [%1], 16, %2;\n" :: "r"(dst + 12288), "l"(Bh + boff), "r"(bp));
        asm volatile("cp.async.cg.shared.global [%0], [%1], 16, %2;\n" :: "r"(dst + 18432), "l"(Bl + boff), "r"(bp));
    };

    const int nch = K >> 4;
    loadChunk(0, 0);
    asm volatile("cp.async.commit_group;\n");

    for (int kc = 0; kc < nch; kc++) {
        if (kc + 1 < nch) {
            loadChunk(kc + 1, (kc + 1) & 1);
            asm volatile("cp.async.commit_group;\n");
            asm volatile("cp.async.wait_group 1;\n");
        } else {
            asm volatile("cp.async.wait_group 0;\n");
        }
        __syncthreads();
        const __nv_bfloat16* sAh = (const __nv_bfloat16*)(smem_raw + (kc & 1)*24576);
        const __nv_bfloat16* sAl = sAh + 3072;
        const __nv_bfloat16* sBh = sAh + 6144;
        const __nv_bfloat16* sBl = sAh + 9216;

        wmma::fragment<wmma::matrix_a,16,16,16,__nv_bfloat16,wmma::row_major> afh[2], afl[2];
        #pragma unroll
        for (int mi = 0; mi < 2; mi++) {
            int r0 = warp_m*32 + mi*16;
            wmma::load_matrix_sync(afh[mi], sAh + r0*24, 24);
            wmma::load_matrix_sync(afl[mi], sAl + r0*24, 24);
        }
        #pragma unroll
        for (int ni = 0; ni < 4; ni++) {
            int rn = warp_n*64 + ni*16;
            wmma::fragment<wmma::matrix_b,16,16,16,__nv_bfloat16,wmma::col_major> bfh, bfl;
            wmma::load_matrix_sync(bfh, sBh + rn*24, 24);
            wmma::load_matrix_sync(bfl, sBl + rn*24, 24);
            #pragma unroll
            for (int mi = 0; mi < 2; mi++) {
                wmma::mma_sync(c[mi][ni], afh[mi], bfh, c[mi][ni]);
                wmma::mma_sync(c[mi][ni], afl[mi], bfh, c[mi][ni]);
                wmma::mma_sync(c[mi][ni], afh[mi], bfl, c[mi][ni]);
            }
        }
        __syncthreads();
    }

    float* stage = (float*)smem_raw;
    #pragma unroll
    for (int p = 0; p < 2; p++) {
        if (warp_n == p) {
            #pragma unroll
            for (int mi = 0; mi < 2; mi++)
                #pragma unroll
                for (int ni = 0; ni < 4; ni++)
                    wmma::store_matrix_sync(stage + (warp_m*32 + mi*16)*68 + ni*16,
                                            c[mi][ni], 68, wmma::mem_row_major);
        }
        __syncthreads();
        for (int e = tid; e < 8192; e += 256) {
            int r  = e >> 6, cc = e & 63;
            int col = n0 + p*64 + cc;
            if (col < Nc)
                Cf[(size_t)(m0 + r)*Nc + col] = stage[r*68 + cc] + bias[col];
        }
        __syncthreads();
    }
}

// ---------------- performer scan (CCH=64, TCH=32), fused feature map ---------
static __device__ __forceinline__ void featrow(
    size_t tok, int h, int off, int lane, float dst[TCH][M_])
{
    const float* f = &g_qkv[tok*QS2_ + off + h*M_];
    float e[M_];
    float s = 0.f;
    #pragma unroll
    for (int m = 0; m < M_; m++) { float x = f[m]; e[m] = expf(-0.5f*x*x); s += e[m]; }
    float inv = 1.f/(s + EPSF);
    #pragma unroll
    for (int m = 0; m < M_; m++) dst[lane][m] = e[m]*inv;
}

__global__ void __launch_bounds__(64) perf_pass1()
{
    int bid = blockIdx.x;
    int c  = bid % CCH;
    int bh = bid / CCH;
    int h = bh % H_, b = bh / H_;
    int t = threadIdx.x;
    __shared__ float kp_s[TCH][M_];
    if (t < TCH)
        featrow((size_t)(b*S_ + c*TCH + t), h, 256, t, kp_s);
    __syncthreads();

    float kv[M_], ks[M_];
    #pragma unroll
    for (int m = 0; m < M_; m++) { kv[m] = 0.f; ks[m] = 0.f; }
    int s0 = c*TCH;
    for (int s = 0; s < TCH; s++) {
        size_t tok = (size_t)(b*S_ + s0 + s);
        float vt = g_qkv[tok*QS2_ + VOFF + h*DK_ + t];
        #pragma unroll
        for (int m = 0; m < M_; m++) { float kpv = kp_s[s][m]; kv[m] += kpv*vt; ks[m] += kpv; }
    }
    size_t cb = ((size_t)bh*CCH + c)*M_;
    #pragma unroll
    for (int m = 0; m < M_; m++) g_ckv[(cb+m)*DK_ + t] = kv[m];
    if (t < M_) g_ck[cb + t] = ks[t];
}

// parallel over (bh, m): one block per scan lane group
__global__ void __launch_bounds__(64) perf_prefix()
{
    int bh = blockIdx.x;
    int m  = blockIdx.y;
    int t = threadIdx.x;
    if (m < M_) {
        float vals[CCH];
        #pragma unroll
        for (int c = 0; c < CCH; c++)
            vals[c] = g_ckv[(((size_t)bh*CCH + c)*M_ + m)*DK_ + t];
        float acc = 0.f;
        #pragma unroll
        for (int c = 0; c < CCH; c++) { float tmp = vals[c]; vals[c] = acc; acc += tmp; }
        #pragma unroll
        for (int c = 0; c < CCH; c++)
            g_ckv[(((size_t)bh*CCH + c)*M_ + m)*DK_ + t] = vals[c];
    } else if (t < M_) {
        float vals[CCH];
        #pragma unroll
        for (int c = 0; c < CCH; c++) vals[c] = g_ck[((size_t)bh*CCH + c)*M_ + t];
        float acc = 0.f;
        #pragma unroll
        for (int c = 0; c < CCH; c++) { float tmp = vals[c]; vals[c] = acc; acc += tmp; }
        #pragma unroll
        for (int c = 0; c < CCH; c++) g_ck[((size_t)bh*CCH + c)*M_ + t] = vals[c];
    }
}

__global__ void __launch_bounds__(64) perf_pass2()
{
    int bid = blockIdx.x;
    int c  = bid % CCH;
    int bh = bid / CCH;
    int h = bh % H_, b = bh / H_;
    int t = threadIdx.x;
    int lane = t & 31;
    int w = t >> 5;
    __shared__ float qp_s[TCH][M_], kp_s[TCH][M_];
    featrow((size_t)(b*S_ + c*TCH + lane), h, w ? 256 : 0, lane, w ? kp_s : qp_s);
    __syncthreads();

    float kv[M_], kc[M_];
    size_t cb = ((size_t)bh*CCH + c)*M_;
    #pragma unroll
    for (int m = 0; m < M_; m++) { kv[m] = g_ckv[(cb+m)*DK_ + t]; kc[m] = g_ck[cb+m]; }
    float gate = g_gate[bh];
    int s0 = c*TCH;
    for (int s = 0; s < TCH; s++) {
        size_t tok = (size_t)(b*S_ + s0 + s);
        float vt = g_qkv[tok*QS2_ + VOFF + h*DK_ + t];
        float num = 0.f, den = 0.f;
        #pragma unroll
        for (int m = 0; m < M_; m++) {
            float kpv = kp_s[s][m]; kv[m] += kpv*vt; kc[m] += kpv;
            float qpv = qp_s[s][m]; num += qpv*kv[m]; den += qpv*kc[m];
        }
        float o = num / (den + EPSF) * gate;
        size_t oi = tok*D_ + h*DK_ + t;
        __nv_bfloat16 hh = __float2bfloat16(o);
        g_ah[oi] = hh;
        g_al[oi] = __float2bfloat16(o - __bfloat162float(hh));
    }
}

// =============================================================================
extern "C" void kernel_launch(void* const* d_in, const int* in_sizes, int n_in,
                              void* d_out, int out_size)
{
    const int*   ids         = (const int*)  d_in[0];
    const int*   user_ids    = (const int*)  d_in[1];
    const float* id_embed    = (const float*)d_in[2];
    const float* feat_proj   = (const float*)d_in[3];
    const float* gamma       = (const float*)d_in[4];
    const float* gate_logits = (const float*)d_in[5];
    const float* wq          = (const float*)d_in[6];
    const float* wk          = (const float*)d_in[7];
    const float* wv          = (const float*)d_in[8];
    const float* wo          = (const float*)d_in[9];
    const float* omega       = (const float*)d_in[10];
    const float* ln1_a       = (const float*)d_in[11];
    const float* ln1_b       = (const float*)d_in[12];
    const float* ln2_a       = (const float*)d_in[13];
    const float* ln2_b       = (const float*)d_in[14];
    const float* ff_w1       = (const float*)d_in[15];
    const float* ff_b1       = (const float*)d_in[16];
    const float* ff_w2       = (const float*)d_in[17];
    const float* ff_b2       = (const float*)d_in[18];
    const float* fin_a       = (const float*)d_in[19];
    const float* fin_b       = (const float*)d_in[20];
    const float* proj_w      = (const float*)d_in[21];
    const float* proj_b      = (const float*)d_in[22];
    const float* feat_tbl    = (const float*)d_in[23];
    /* d_in[24] = prod_mask (derived as ids>=10) */
    const float* pe          = (const float*)d_in[25];
    float* out = (float*)d_out;

    float *px, *pqkv;
    __nv_bfloat16 *pxh, *pxl, *pah, *pal, *ph1h, *ph1l, *pwh, *pwl;
    cudaGetSymbolAddress((void**)&px,   g_x);
    cudaGetSymbolAddress((void**)&pxh,  g_xh);
    cudaGetSymbolAddress((void**)&pxl,  g_xl);
    cudaGetSymbolAddress((void**)&pqkv, g_qkv);
    cudaGetSymbolAddress((void**)&pah,  g_ah);
    cudaGetSymbolAddress((void**)&pal,  g_al);
    cudaGetSymbolAddress((void**)&ph1h, g_h1h);
    cudaGetSymbolAddress((void**)&ph1l, g_h1l);
    cudaGetSymbolAddress((void**)&pwh,  g_wh);
    cudaGetSymbolAddress((void**)&pwl,  g_wl);

    bool deep = true;
    deep &= (cudaFuncSetAttribute(tgemm4<0>, cudaFuncAttributeMaxDynamicSharedMemorySize, TG4_SMEM) == cudaSuccess);
    deep &= (cudaFuncSetAttribute(tgemm4<2>, cudaFuncAttributeMaxDynamicSharedMemorySize, TG4_SMEM) == cudaSuccess);
    deep &= (cudaFuncSetAttribute(tgemm4<3>, cudaFuncAttributeMaxDynamicSharedMemorySize, TG4_SMEM) == cudaSuccess);
    deep &= (cudaFuncSetAttribute(tgemm4<4>, cudaFuncAttributeMaxDynamicSharedMemorySize, TG4_SMEM) == cudaSuccess);
    deep &= (cudaGetLastError() == cudaSuccess);

    dim3 gFoldAll(D_/128, H_, 2*L_);
    dim3 gQKV(QS2_/128, BS_/128);    // (12, 32)
    dim3 gDD (D_/128,   BS_/128);    // (8, 32)
    dim3 gDF (DFF_/128, BS_/128);    // (32, 32)
    dim3 gVT (1, 32);
    dim3 gPfx(B_*H_, M_+1);          // (32, 17)

    const int GB_V    = (int)((DD_/8 + 255)/256);
    dim3 gVsplit(GB_V, L_);
    const int GB_WO   = (int)((4*DD_/8 + 255)/256);
    const int GB_FF   = (int)((16*DD_/8 + 255)/256);
    const int GB_PROJ = (int)(((size_t)VT_*D_/8 + 255)/256);

    #define RUN_TG(E, GRID, AH, AL, BH, BL, BI, RS, CF, CH, CL, NC, KK)            \
        do {                                                                        \
            if (deep) tgemm4<E><<<GRID, 256, TG4_SMEM>>>(AH, AL, BH, BL, BI, RS,    \
                                                         CF, CH, CL, NC, KK);       \
            else      tgemm2<E><<<GRID, 256>>>(AH, AL, BH, BL, BI, RS,              \
                                               CF, CH, CL, NC, KK);                 \
        } while (0)

    embtbl_kernel<<<VS_, 256>>>(id_embed, feat_proj, gamma, feat_tbl);
    xinit_kernel<<<(BS_*D_ + 255)/256, 256>>>(ids, pe);
    featfold_kernel<<<gFoldAll, 256>>>(wq, wk, omega);
    wsplitv_kernel<<<gVsplit, 256>>>((const float4*)wv);
    ln_kernel<<<BS_, 256>>>(px, ln1_a, ln1_b, pxh, pxl);
    RUN_TG(0, gQKV, pxh, pxl, pwh + OFF_QKV, pwl + OFF_QKV,
           (const float*)nullptr, (const float*)nullptr,
           pqkv, (__nv_bfloat16*)nullptr, (__nv_bfloat16*)nullptr, QS2_, D_);

    gate_kernel<<<B_, 32>>>(user_ids, gate_logits);
    wsplit_kernel<<<GB_WO,   256>>>((const float4*)wo,     (size_t)4*DD_/8,  OFF_WO);
    wsplit_kernel<<<GB_FF,   256>>>((const float4*)ff_w1,  (size_t)16*DD_/8, OFF_FF1);
    wsplit_kernel<<<GB_FF,   256>>>((const float4*)ff_w2,  (size_t)16*DD_/8, OFF_FF2);
    wsplit_kernel<<<GB_PROJ, 256>>>((const float4*)proj_w, (size_t)VT_*D_/8, OFF_PROJ);

    for (int l = 0; l < L_; l++) {
        if (l > 0) {
            ln_kernel<<<BS_, 256>>>(px, ln1_a + l*D_, ln1_b + l*D_, pxh, pxl);
            RUN_TG(0, gQKV, pxh, pxl,
                   pwh + OFF_QKV + (size_t)l*R_QKV, pwl + OFF_QKV + (size_t)l*R_QKV,
                   (const float*)nullptr, (const float*)nullptr,
                   pqkv, (__nv_bfloat16*)nullptr, (__nv_bfloat16*)nullptr, QS2_, D_);
        }
        perf_pass1<<<B_*H_*CCH, 64>>>();
        perf_prefix<<<gPfx, 64>>>();
        perf_pass2<<<B_*H_*CCH, 64>>>();
        RUN_TG(3, gDD, pah, pal,
               pwh + OFF_WO + (size_t)l*DD_, pwl + OFF_WO + (size_t)l*DD_,
               (const float*)nullptr, px,
               px, (__nv_bfloat16*)nullptr, (__nv_bfloat16*)nullptr, D_, D_);
        ln_kernel<<<BS_, 256>>>(px, ln2_a + l*D_, ln2_b + l*D_, pxh, pxl);
        RUN_TG(2, gDF, pxh, pxl,
               pwh + OFF_FF1 + (size_t)l*4*DD_, pwl + OFF_FF1 + (size_t)l*4*DD_,
               ff_b1 + (size_t)l*DFF_, (const float*)nullptr,
               (float*)nullptr, ph1h, ph1l, DFF_, D_);
        RUN_TG(4, gDD, ph1h, ph1l,
               pwh + OFF_FF2 + (size_t)l*4*DD_, pwl + OFF_FF2 + (size_t)l*4*DD_,
               ff_b2 + (size_t)l*D_, px,
               px, (__nv_bfloat16*)nullptr, (__nv_bfloat16*)nullptr, D_, DFF_);
    }

    ln_kernel<<<BS_, 256>>>(px, fin_a, fin_b, pxh, pxl);
    bgemm_proj<<<gVT, 256>>>(pxh, pxl, pwh + OFF_PROJ, pwl + OFF_PROJ,
                             proj_b, out, VT_, D_);
}

// round 16
// speedup vs baseline: 1.0064x; 1.0064x over previous
#include <cuda_runtime.h>
#include <cuda_bf16.h>
#include <mma.h>
#include <math.h>
#include <stdint.h>

using namespace nvcuda;

#define B_   2
#define S_   2048
#define D_   1024
#define H_   16
#define DK_  64
#define M_   16
#define L_   4
#define DFF_ 4096
#define VT_  69
#define VS_  69
#define FD_  34
#define BS_  (B_*S_)
#define QS2_ 1536            // packed [qfeat 256 | kfeat 256 | v 1024]
#define VOFF 512
#define CCH  64
#define TCH  32
#define EPSF 1e-6f

#define DD_       ((size_t)D_*D_)
#define R_QKV     ((size_t)QS2_*D_)
#define OFF_QKV   ((size_t)0)
#define OFF_WO    ((size_t)L_*R_QKV)
#define OFF_FF1   (OFF_WO  + (size_t)L_*DD_)
#define OFF_FF2   (OFF_FF1 + (size_t)L_*4*DD_)
#define OFF_PROJ  (OFF_FF2 + (size_t)L_*4*DD_)
#define WTOT      (OFF_PROJ + (size_t)VT_*D_)

// ---------------- scratch ----------------------------------------------------
__device__ __align__(16) float g_emb2[VS_*D_];
__device__ __align__(16) float g_x   [BS_*D_];
__device__ __align__(16) __nv_bfloat16 g_xh[BS_*D_];
__device__ __align__(16) __nv_bfloat16 g_xl[BS_*D_];
__device__ __align__(16) float g_qkv [(size_t)BS_*QS2_];
__device__ __align__(16) __nv_bfloat16 g_ah[BS_*D_];
__device__ __align__(16) __nv_bfloat16 g_al[BS_*D_];
__device__ __align__(16) __nv_bfloat16 g_h1h[(size_t)BS_*DFF_];
__device__ __align__(16) __nv_bfloat16 g_h1l[(size_t)BS_*DFF_];
__device__ __align__(16) __nv_bfloat16 g_wh[WTOT];
__device__ __align__(16) __nv_bfloat16 g_wl[WTOT];
__device__ __align__(16) float g_ckv[(size_t)B_*H_*CCH*M_*DK_];
__device__ __align__(16) float g_ck [B_*H_*CCH*M_];
__device__ float g_gate[B_*H_];

// ---------------- helpers -----------------------------------------------------
static __device__ __forceinline__ uint32_t pack_hi(float a, float b, uint32_t& lo)
{
    __nv_bfloat16 ha = __float2bfloat16(a), hb = __float2bfloat16(b);
    __nv_bfloat162 h = __halves2bfloat162(ha, hb);
    __nv_bfloat162 l = __halves2bfloat162(__float2bfloat16(a - __bfloat162float(ha)),
                                          __float2bfloat16(b - __bfloat162float(hb)));
    lo = *(uint32_t*)&l;
    return *(uint32_t*)&h;
}

// ---------------- weight split: 8 floats/thread, 16B coalesced stores --------
__global__ void wsplit_kernel(const float4* __restrict__ src, size_t n16, size_t dstOff)
{
    uint4* wh4 = (uint4*)(g_wh + dstOff);
    uint4* wl4 = (uint4*)(g_wl + dstOff);
    for (size_t i = (size_t)blockIdx.x*blockDim.x + threadIdx.x; i < n16;
         i += (size_t)gridDim.x*blockDim.x) {
        float4 v0 = src[i*2];
        float4 v1 = src[i*2 + 1];
        uint4 uh, ul;
        uh.x = pack_hi(v0.x, v0.y, ul.x);
        uh.y = pack_hi(v0.z, v0.w, ul.y);
        uh.z = pack_hi(v1.x, v1.y, ul.z);
        uh.w = pack_hi(v1.z, v1.w, ul.w);
        wh4[i] = uh;
        wl4[i] = ul;
    }
}

// v-panels for all layers in one launch (blockIdx.y = layer)
__global__ void wsplitv_kernel(const float4* __restrict__ wv)
{
    int l = blockIdx.y;
    const float4* src = wv + (size_t)l*DD_/4;
    size_t dstOff = OFF_QKV + (size_t)l*R_QKV + (size_t)VOFF*D_;
    uint4* wh4 = (uint4*)(g_wh + dstOff);
    uint4* wl4 = (uint4*)(g_wl + dstOff);
    size_t n16 = DD_/8;
    for (size_t i = (size_t)blockIdx.x*blockDim.x + threadIdx.x; i < n16;
         i += (size_t)gridDim.x*blockDim.x) {
        float4 v0 = src[i*2];
        float4 v1 = src[i*2 + 1];
        uint4 uh, ul;
        uh.x = pack_hi(v0.x, v0.y, ul.x);
        uh.y = pack_hi(v0.z, v0.w, ul.y);
        uh.z = pack_hi(v1.x, v1.y, ul.z);
        uh.w = pack_hi(v1.z, v1.w, ul.w);
        wh4[i] = uh;
        wl4[i] = ul;
    }
}

// ---------------- fold omega into wq/wk — all layers, one launch --------------
// blockIdx.z = l*2 + (0:q, 1:k)
__global__ void __launch_bounds__(256) featfold_kernel(
    const float* __restrict__ wq, const float* __restrict__ wk,
    const float* __restrict__ omega)
{
    int z = blockIdx.z;
    int l = z >> 1;
    int isK = z & 1;
    const float* w = (isK ? wk : wq) + (size_t)l*DD_;
    const float* om = omega + (size_t)l*M_*DK_;
    size_t dstRowBase = OFF_QKV + (size_t)l*R_QKV + (isK ? (size_t)256*D_ : 0);
    int h = blockIdx.y;
    int dl = threadIdx.x & 127;
    int seg = threadIdx.x >> 7;
    int d = blockIdx.x*128 + dl;
    __shared__ float so[M_][DK_];
    __shared__ float red[128][M_];
    for (int i = threadIdx.x; i < M_*DK_; i += 256) so[i/DK_][i%DK_] = om[i];
    __syncthreads();
    float acc[M_];
    #pragma unroll
    for (int m = 0; m < M_; m++) acc[m] = 0.f;
    const float* wp = w + (size_t)(h*DK_ + seg*32)*D_ + d;
    #pragma unroll 8
    for (int dk = 0; dk < 32; dk++) {
        float wv = wp[(size_t)dk*D_];
        #pragma unroll
        for (int m = 0; m < M_; m++) acc[m] += so[m][seg*32 + dk]*wv;
    }
    if (seg == 1) {
        #pragma unroll
        for (int m = 0; m < M_; m++) red[dl][m] = acc[m];
    }
    __syncthreads();
    if (seg == 0) {
        #pragma unroll
        for (int m = 0; m < M_; m++) {
            float v = acc[m] + red[dl][m];
            __nv_bfloat16 hh = __float2bfloat16(v);
            size_t oi = dstRowBase + (size_t)(h*M_+m)*D_ + d;
            g_wh[oi] = hh;
            g_wl[oi] = __float2bfloat16(v - __bfloat162float(hh));
        }
    }
}

// ---------------- embedding / init / gate ------------------------------------
__global__ void embtbl_kernel(const float* __restrict__ id_embed,
                              const float* __restrict__ feat_proj,
                              const float* __restrict__ gammap,
                              const float* __restrict__ feat_tbl)
{
    int v = blockIdx.x;
    float gscale = gammap[0] * ((v >= 10) ? 1.f : 0.f);
    __shared__ float ft[FD_];
    if (threadIdx.x < FD_) ft[threadIdx.x] = feat_tbl[v*FD_ + threadIdx.x];
    __syncthreads();
    for (int d = threadIdx.x; d < D_; d += blockDim.x) {
        float dot = 0.f;
        #pragma unroll
        for (int f = 0; f < FD_; f++) dot += ft[f] * feat_proj[d*FD_ + f];
        g_emb2[v*D_ + d] = id_embed[(size_t)v*D_ + d] + gscale * dot;
    }
}

__global__ void xinit_kernel(const int* __restrict__ ids, const float* __restrict__ pe)
{
    int idx = blockIdx.x*blockDim.x + threadIdx.x;
    if (idx >= BS_*D_) return;
    int d = idx % D_;
    int bs = idx / D_;
    int s = bs % S_;
    g_x[idx] = g_emb2[ids[bs]*D_ + d] + pe[(size_t)s*D_ + d];
}

__global__ void gate_kernel(const int* __restrict__ user_ids,
                            const float* __restrict__ gl)
{
    int b = blockIdx.x;
    int lane = threadIdx.x;
    float v = (lane < H_) ? gl[(size_t)user_ids[b]*H_ + lane] : -1e30f;
    float mx = v;
    #pragma unroll
    for (int o = 16; o > 0; o >>= 1) mx = fmaxf(mx, __shfl_xor_sync(~0u, mx, o));
    float e = (lane < H_) ? expf(v - mx) : 0.f;
    float s = e;
    #pragma unroll
    for (int o = 16; o > 0; o >>= 1) s += __shfl_xor_sync(~0u, s, o);
    if (lane < H_) g_gate[b*H_ + lane] = e / s;
}

// ---------------- LayerNorm -> bf16 hi/lo (vectorized) ------------------------
__global__ void __launch_bounds__(256) ln_kernel(const float* __restrict__ X,
                                                 const float* __restrict__ alpha,
                                                 const float* __restrict__ beta,
                                                 __nv_bfloat16* __restrict__ Yh,
                                                 __nv_bfloat16* __restrict__ Yl)
{
    int row = blockIdx.x;
    int tid = threadIdx.x;
    const float4* x4 = (const float4*)(X + (size_t)row*D_);
    float4 v = x4[tid];
    float s  = v.x + v.y + v.z + v.w;
    float s2 = v.x*v.x + v.y*v.y + v.z*v.z + v.w*v.w;

    __shared__ float red[64];
    #pragma unroll
    for (int o = 16; o > 0; o >>= 1) {
        s  += __shfl_down_sync(~0u, s,  o);
        s2 += __shfl_down_sync(~0u, s2, o);
    }
    int w = tid >> 5, lane = tid & 31;
    if (lane == 0) { red[w] = s; red[w+32] = s2; }
    __syncthreads();
    if (w == 0) {
        s  = (lane < 8) ? red[lane]    : 0.f;
        s2 = (lane < 8) ? red[lane+32] : 0.f;
        #pragma unroll
        for (int o = 4; o > 0; o >>= 1) {
            s  += __shfl_down_sync(~0u, s,  o);
            s2 += __shfl_down_sync(~0u, s2, o);
        }
        if (lane == 0) { red[0] = s; red[1] = s2; }
    }
    __syncthreads();
    float mu  = red[0] / (float)D_;
    float var = (red[1] - (float)D_*mu*mu) / (float)(D_-1);
    float inv = 1.f / (sqrtf(fmaxf(var, 0.f)) + EPSF);

    float4 a4 = ((const float4*)alpha)[tid];
    float4 b4 = ((const float4*)beta)[tid];
    float o0 = a4.x*(v.x - mu)*inv + b4.x;
    float o1 = a4.y*(v.y - mu)*inv + b4.y;
    float o2 = a4.z*(v.z - mu)*inv + b4.z;
    float o3 = a4.w*(v.w - mu)*inv + b4.w;

    uint2 uh, ul;
    uh.x = pack_hi(o0, o1, ul.x);
    uh.y = pack_hi(o2, o3, ul.y);
    ((uint2*)(Yh + (size_t)row*D_))[tid] = uh;
    ((uint2*)(Yl + (size_t)row*D_))[tid] = ul;
}

// =============================================================================
//  split-bf16 mma.sync GEMM primitives
// =============================================================================
#define ROWB 48
#define STG_BYTES 24576
#define TG4_SMEM  (4u*STG_BYTES)   // 98304

static __device__ __forceinline__ void cpa16s(uint32_t dst, const void* src) {
    asm volatile("cp.async.cg.shared.global [%0], [%1], 16;" :: "r"(dst), "l"(src));
}
static __device__ __forceinline__ void ldm4(uint32_t* d, uint32_t a) {
    asm volatile("ldmatrix.sync.aligned.m8n8.x4.shared.b16 {%0,%1,%2,%3}, [%4];"
                 : "=r"(d[0]), "=r"(d[1]), "=r"(d[2]), "=r"(d[3]) : "r"(a));
}
static __device__ __forceinline__ void mma16816(float* c, const uint32_t* a, const uint32_t* b) {
    asm volatile("mma.sync.aligned.m16n8k16.row.col.f32.bf16.bf16.f32 "
                 "{%0,%1,%2,%3},{%4,%5,%6,%7},{%8,%9},{%0,%1,%2,%3};"
                 : "+f"(c[0]), "+f"(c[1]), "+f"(c[2]), "+f"(c[3])
                 : "r"(a[0]), "r"(a[1]), "r"(a[2]), "r"(a[3]), "r"(b[0]), "r"(b[1]));
}

template<int EPI>
static __device__ __forceinline__ void epi_pair(
    float v0, float v1, int rr, int cc, size_t gi,
    const float* bias, const float* res,
    float* Cf, __nv_bfloat16* Ch, __nv_bfloat16* Cl)
{
    if (EPI == 2) {
        v0 += bias[cc]; v1 += bias[cc+1];
        float x0 = v0, x1 = v1;
        v0 = 0.5f*x0*(1.f + tanhf(0.7978845608028654f*(x0 + 0.044715f*x0*x0*x0)));
        v1 = 0.5f*x1*(1.f + tanhf(0.7978845608028654f*(x1 + 0.044715f*x1*x1*x1)));
        __nv_bfloat16 h0 = __float2bfloat16(v0), h1 = __float2bfloat16(v1);
        *(__nv_bfloat162*)(Ch + gi) = __halves2bfloat162(h0, h1);
        *(__nv_bfloat162*)(Cl + gi) = __halves2bfloat162(
            __float2bfloat16(v0 - __bfloat162float(h0)),
            __float2bfloat16(v1 - __bfloat162float(h1)));
    } else {
        if (EPI == 3) { float2 r = *(const float2*)(res + gi); v0 += r.x; v1 += r.y; }
        if (EPI == 4) {
            float2 r = *(const float2*)(res + gi);
            v0 += bias[cc] + r.x; v1 += bias[cc+1] + r.y;
        }
        *(float2*)(Cf + gi) = make_float2(v0, v1);
    }
}

// shared per-chunk compute (128x128 tile, warp = 32x64)
static __device__ __forceinline__ void tg_compute(
    float acc[2][8][4], uint32_t bb, uint32_t aoff, uint32_t boff)
{
    uint32_t aH[2][4], aL[2][4];
    ldm4(aH[0], bb + aoff);
    ldm4(aH[1], bb + aoff + 16*ROWB);
    ldm4(aL[0], bb + 6144 + aoff);
    ldm4(aL[1], bb + 6144 + aoff + 16*ROWB);

    #pragma unroll
    for (int half = 0; half < 2; half++) {
        uint32_t bH[2][4], bL[2][4];
        uint32_t bo = boff + half*32*ROWB;
        ldm4(bH[0], bb + 12288 + bo);
        ldm4(bH[1], bb + 12288 + bo + 16*ROWB);
        ldm4(bL[0], bb + 18432 + bo);
        ldm4(bL[1], bb + 18432 + bo + 16*ROWB);
        #pragma unroll
        for (int t = 0; t < 4; t++) {
            int nj = half*4 + t;
            const uint32_t* bh = &bH[t >> 1][(t & 1)*2];
            const uint32_t* bl = &bL[t >> 1][(t & 1)*2];
            #pragma unroll
            for (int mi = 0; mi < 2; mi++) {
                mma16816(acc[mi][nj], aH[mi], bh);
                mma16816(acc[mi][nj], aL[mi], bh);
                mma16816(acc[mi][nj], aH[mi], bl);
            }
        }
    }
}

template<int EPI>
static __device__ __forceinline__ void tg_epilogue(
    float acc[2][8][4], int m0, int n0, int wm, int wn, int lane,
    const float* bias, const float* res,
    float* Cf, __nv_bfloat16* Ch, __nv_bfloat16* Cl, int Nc)
{
    const int gq = lane >> 2;
    const int qp = lane & 3;
    #pragma unroll
    for (int mi = 0; mi < 2; mi++) {
        #pragma unroll
        for (int nj = 0; nj < 8; nj++) {
            int r0 = m0 + wm*32 + mi*16 + gq;
            int cc = n0 + wn*64 + nj*8 + qp*2;
            #pragma unroll
            for (int hrow = 0; hrow < 2; hrow++) {
                int rr = r0 + hrow*8;
                epi_pair<EPI>(acc[mi][nj][hrow*2], acc[mi][nj][hrow*2+1],
                              rr, cc, (size_t)rr*Nc + cc, bias, res, Cf, Ch, Cl);
            }
        }
    }
}

// ---- 4-stage, single-sync-per-chunk, dynamic smem (proven optimum) ----------
template<int EPI>
__global__ void __launch_bounds__(256, 2) tgemm4(
    const __nv_bfloat16* __restrict__ Ah, const __nv_bfloat16* __restrict__ Al,
    const __nv_bfloat16* __restrict__ Bh, const __nv_bfloat16* __restrict__ Bl,
    const float* __restrict__ bias, const float* __restrict__ res,
    float* __restrict__ Cf, __nv_bfloat16* __restrict__ Ch, __nv_bfloat16* __restrict__ Cl,
    int Nc, int K)
{
    extern __shared__ __align__(16) unsigned char sm4[];
    const uint32_t smB = (uint32_t)__cvta_generic_to_shared(sm4);

    const int tid  = threadIdx.x;
    const int wid  = tid >> 5;
    const int lane = tid & 31;
    const int wm   = wid >> 1;
    const int wn   = wid & 1;
    const int m0 = blockIdx.y * 128;
    const int n0 = blockIdx.x * 128;

    float acc[2][8][4];
    #pragma unroll
    for (int i = 0; i < 2; i++)
        #pragma unroll
        for (int j = 0; j < 8; j++)
            #pragma unroll
            for (int q = 0; q < 4; q++) acc[i][j][q] = 0.f;

    const int crow = tid >> 1, cq = tid & 1;
    const uint32_t cdst = (uint32_t)(crow*ROWB + cq*16);
    const size_t  asrc = (size_t)(m0 + crow)*K + cq*8;
    const size_t  bsrc = (size_t)(n0 + crow)*K + cq*8;

    const uint32_t aoff = (uint32_t)((wm*32 + (lane & 15))*ROWB + (lane >> 4)*16);
    const uint32_t boff = (uint32_t)((wn*64 + ((lane >> 4) << 3) + (lane & 7))*ROWB
                                     + ((lane >> 3) & 1)*16);

    auto loadChunk = [&](int c, int buf) {
        uint32_t bb = smB + (uint32_t)buf*STG_BYTES + cdst;
        int k0 = c*16;
        cpa16s(bb,         Ah + asrc + k0);
        cpa16s(bb +  6144, Al + asrc + k0);
        cpa16s(bb + 12288, Bh + bsrc + k0);
        cpa16s(bb + 18432, Bl + bsrc + k0);
        asm volatile("cp.async.commit_group;");
    };

    const int nch = K >> 4;
    loadChunk(0, 0);
    loadChunk(1, 1);

    for (int c = 0; c < nch; c++) {
        if (c + 2 < nch) {
            loadChunk(c + 2, (c + 2) & 3);
            asm volatile("cp.async.wait_group 2;");
        } else if (c + 1 < nch) {
            asm volatile("cp.async.wait_group 1;");
        } else {
            asm volatile("cp.async.wait_group 0;");
        }
        __syncthreads();
        tg_compute(acc, smB + (uint32_t)(c & 3)*STG_BYTES, aoff, boff);
    }

    tg_epilogue<EPI>(acc, m0, n0, wm, wn, lane, bias, res, Cf, Ch, Cl, Nc);
}

// ---- 2-stage static-smem fallback (proven) ----------------------------------
template<int EPI>
__global__ void __launch_bounds__(256, 2) tgemm2(
    const __nv_bfloat16* __restrict__ Ah, const __nv_bfloat16* __restrict__ Al,
    const __nv_bfloat16* __restrict__ Bh, const __nv_bfloat16* __restrict__ Bl,
    const float* __restrict__ bias, const float* __restrict__ res,
    float* __restrict__ Cf, __nv_bfloat16* __restrict__ Ch, __nv_bfloat16* __restrict__ Cl,
    int Nc, int K)
{
    __shared__ __align__(16) unsigned char sm[2*STG_BYTES];
    const uint32_t smB = (uint32_t)__cvta_generic_to_shared(sm);

    const int tid  = threadIdx.x;
    const int wid  = tid >> 5;
    const int lane = tid & 31;
    const int wm   = wid >> 1;
    const int wn   = wid & 1;
    const int m0 = blockIdx.y * 128;
    const int n0 = blockIdx.x * 128;

    float acc[2][8][4];
    #pragma unroll
    for (int i = 0; i < 2; i++)
        #pragma unroll
        for (int j = 0; j < 8; j++)
            #pragma unroll
            for (int q = 0; q < 4; q++) acc[i][j][q] = 0.f;

    const int crow = tid >> 1, cq = tid & 1;
    const uint32_t cdst = (uint32_t)(crow*ROWB + cq*16);
    const size_t  asrc = (size_t)(m0 + crow)*K + cq*8;
    const size_t  bsrc = (size_t)(n0 + crow)*K + cq*8;

    const uint32_t aoff = (uint32_t)((wm*32 + (lane & 15))*ROWB + (lane >> 4)*16);
    const uint32_t boff = (uint32_t)((wn*64 + ((lane >> 4) << 3) + (lane & 7))*ROWB
                                     + ((lane >> 3) & 1)*16);

    auto loadChunk = [&](int c, int buf) {
        uint32_t bb = smB + (uint32_t)buf*STG_BYTES + cdst;
        int k0 = c*16;
        cpa16s(bb,         Ah + asrc + k0);
        cpa16s(bb +  6144, Al + asrc + k0);
        cpa16s(bb + 12288, Bh + bsrc + k0);
        cpa16s(bb + 18432, Bl + bsrc + k0);
        asm volatile("cp.async.commit_group;");
    };

    const int nch = K >> 4;
    loadChunk(0, 0);

    for (int c = 0; c < nch; c++) {
        if (c + 1 < nch) {
            loadChunk(c + 1, (c + 1) & 1);
            asm volatile("cp.async.wait_group 1;");
        } else {
            asm volatile("cp.async.wait_group 0;");
        }
        __syncthreads();
        tg_compute(acc, smB + (uint32_t)(c & 1)*STG_BYTES, aoff, boff);
        __syncthreads();
    }

    tg_epilogue<EPI>(acc, m0, n0, wm, wn, lane, bias, res, Cf, Ch, Cl, Nc);
}

// ---------------- wmma GEMM for the tiny VT=69 projection --------------------
__global__ void __launch_bounds__(256, 2) bgemm_proj(
    const __nv_bfloat16* __restrict__ Ah, const __nv_bfloat16* __restrict__ Al,
    const __nv_bfloat16* __restrict__ Bh, const __nv_bfloat16* __restrict__ Bl,
    const float* __restrict__ bias, float* __restrict__ Cf, int Nc, int K)
{
    __shared__ __align__(16) unsigned char smem_raw[49152];
    const int tid = threadIdx.x;
    const int warpId = tid >> 5;
    const int warp_m = warpId & 3;
    const int warp_n = warpId >> 2;
    const int m0 = blockIdx.y * 128;
    const int n0 = blockIdx.x * 128;

    wmma::fragment<wmma::accumulator,16,16,16,float> c[2][4];
    #pragma unroll
    for (int i = 0; i < 2; i++)
        #pragma unroll
        for (int j = 0; j < 4; j++) wmma::fill_fragment(c[i][j], 0.f);

    const int row  = tid >> 1;
    const int half = tid & 1;

    auto loadChunk = [&](int kc, int buf) {
        const int k0 = kc * 16;
        size_t aoff = (size_t)(m0 + row)*K + k0 + half*8;
        int brow = n0 + row;
        int bp = (brow < Nc) ? 16 : 0;
        size_t boff = (size_t)(bp ? brow : 0)*K + k0 + half*8;
        unsigned dst = (unsigned)__cvta_generic_to_shared(
            smem_raw + buf*24576 + (row*24 + half*8)*2);
        asm volatile("cp.async.cg.shared.global [%0], [%1], 16;\n" :: "r"(dst), "l"(Ah + aoff));
        asm volatile("cp.async.cg.shared.global [%0], [%1], 16;\n" :: "r"(dst + 6144), "l"(Al + aoff));
        asm volatile("cp.async.cg.shared.global [%0], [%1], 16, %2;\n" :: "r"(dst + 12288), "l"(Bh + boff), "r"(bp));
        asm volatile("cp.async.cg.shared.global [%0], [%1], 16, %2;\n" :: "r"(dst + 18432), "l"(Bl + boff), "r"(bp));
    };

    const int nch = K >> 4;
    loadChunk(0, 0);
    asm volatile("cp.async.commit_group;\n");

    for (int kc = 0; kc < nch; kc++) {
        if (kc + 1 < nch) {
            loadChunk(kc + 1, (kc + 1) & 1);
            asm volatile("cp.async.commit_group;\n");
            asm volatile("cp.async.wait_group 1;\n");
        } else {
            asm volatile("cp.async.wait_group 0;\n");
        }
        __syncthreads();
        const __nv_bfloat16* sAh = (const __nv_bfloat16*)(smem_raw + (kc & 1)*24576);
        const __nv_bfloat16* sAl = sAh + 3072;
        const __nv_bfloat16* sBh = sAh + 6144;
        const __nv_bfloat16* sBl = sAh + 9216;

        wmma::fragment<wmma::matrix_a,16,16,16,__nv_bfloat16,wmma::row_major> afh[2], afl[2];
        #pragma unroll
        for (int mi = 0; mi < 2; mi++) {
            int r0 = warp_m*32 + mi*16;
            wmma::load_matrix_sync(afh[mi], sAh + r0*24, 24);
            wmma::load_matrix_sync(afl[mi], sAl + r0*24, 24);
        }
        #pragma unroll
        for (int ni = 0; ni < 4; ni++) {
            int rn = warp_n*64 + ni*16;
            wmma::fragment<wmma::matrix_b,16,16,16,__nv_bfloat16,wmma::col_major> bfh, bfl;
            wmma::load_matrix_sync(bfh, sBh + rn*24, 24);
            wmma::load_matrix_sync(bfl, sBl + rn*24, 24);
            #pragma unroll
            for (int mi = 0; mi < 2; mi++) {
                wmma::mma_sync(c[mi][ni], afh[mi], bfh, c[mi][ni]);
                wmma::mma_sync(c[mi][ni], afl[mi], bfh, c[mi][ni]);
                wmma::mma_sync(c[mi][ni], afh[mi], bfl, c[mi][ni]);
            }
        }
        __syncthreads();
    }

    float* stage = (float*)smem_raw;
    #pragma unroll
    for (int p = 0; p < 2; p++) {
        if (warp_n == p) {
            #pragma unroll
            for (int mi = 0; mi < 2; mi++)
                #pragma unroll
                for (int ni = 0; ni < 4; ni++)
                    wmma::store_matrix_sync(stage + (warp_m*32 + mi*16)*68 + ni*16,
                                            c[mi][ni], 68, wmma::mem_row_major);
        }
        __syncthreads();
        for (int e = tid; e < 8192; e += 256) {
            int r  = e >> 6, cc = e & 63;
            int col = n0 + p*64 + cc;
            if (col < Nc)
                Cf[(size_t)(m0 + r)*Nc + col] = stage[r*68 + cc] + bias[col];
        }
        __syncthreads();
    }
}

// ---------------- performer scan (CCH=64, TCH=32), fused feature map ---------
static __device__ __forceinline__ void featrow(
    size_t tok, int h, int off, int lane, float dst[TCH][M_])
{
    const float* f = &g_qkv[tok*QS2_ + off + h*M_];
    float e[M_];
    float s = 0.f;
    #pragma unroll
    for (int m = 0; m < M_; m++) { float x = f[m]; e[m] = expf(-0.5f*x*x); s += e[m]; }
    float inv = 1.f/(s + EPSF);
    #pragma unroll
    for (int m = 0; m < M_; m++) dst[lane][m] = e[m]*inv;
}

__global__ void __launch_bounds__(64) perf_pass1()
{
    int bid = blockIdx.x;
    int c  = bid % CCH;
    int bh = bid / CCH;
    int h = bh % H_, b = bh / H_;
    int t = threadIdx.x;
    __shared__ float kp_s[TCH][M_];
    if (t < TCH)
        featrow((size_t)(b*S_ + c*TCH + t), h, 256, t, kp_s);
    __syncthreads();

    float kv[M_], ks[M_];
    #pragma unroll
    for (int m = 0; m < M_; m++) { kv[m] = 0.f; ks[m] = 0.f; }
    int s0 = c*TCH;
    for (int s = 0; s < TCH; s++) {
        size_t tok = (size_t)(b*S_ + s0 + s);
        float vt = g_qkv[tok*QS2_ + VOFF + h*DK_ + t];
        #pragma unroll
        for (int m = 0; m < M_; m++) { float kpv = kp_s[s][m]; kv[m] += kpv*vt; ks[m] += kpv; }
    }
    size_t cb = ((size_t)bh*CCH + c)*M_;
    #pragma unroll
    for (int m = 0; m < M_; m++) g_ckv[(cb+m)*DK_ + t] = kv[m];
    if (t < M_) g_ck[cb + t] = ks[t];
}

// parallel over (bh, m): one block per scan lane group
__global__ void __launch_bounds__(64) perf_prefix()
{
    int bh = blockIdx.x;
    int m  = blockIdx.y;
    int t = threadIdx.x;
    if (m < M_) {
        float vals[CCH];
        #pragma unroll
        for (int c = 0; c < CCH; c++)
            vals[c] = g_ckv[(((size_t)bh*CCH + c)*M_ + m)*DK_ + t];
        float acc = 0.f;
        #pragma unroll
        for (int c = 0; c < CCH; c++) { float tmp = vals[c]; vals[c] = acc; acc += tmp; }
        #pragma unroll
        for (int c = 0; c < CCH; c++)
            g_ckv[(((size_t)bh*CCH + c)*M_ + m)*DK_ + t] = vals[c];
    } else if (t < M_) {
        float vals[CCH];
        #pragma unroll
        for (int c = 0; c < CCH; c++) vals[c] = g_ck[((size_t)bh*CCH + c)*M_ + t];
        float acc = 0.f;
        #pragma unroll
        for (int c = 0; c < CCH; c++) { float tmp = vals[c]; vals[c] = acc; acc += tmp; }
        #pragma unroll
        for (int c = 0; c < CCH; c++) g_ck[((size_t)bh*CCH + c)*M_ + t] = vals[c];
    }
}

__global__ void __launch_bounds__(64) perf_pass2()
{
    int bid = blockIdx.x;
    int c  = bid % CCH;
    int bh = bid / CCH;
    int h = bh % H_, b = bh / H_;
    int t = threadIdx.x;
    int lane = t & 31;
    int w = t >> 5;
    __shared__ float qp_s[TCH][M_], kp_s[TCH][M_];
    featrow((size_t)(b*S_ + c*TCH + lane), h, w ? 256 : 0, lane, w ? kp_s : qp_s);
    __syncthreads();

    float kv[M_], kc[M_];
    size_t cb = ((size_t)bh*CCH + c)*M_;
    #pragma unroll
    for (int m = 0; m < M_; m++) { kv[m] = g_ckv[(cb+m)*DK_ + t]; kc[m] = g_ck[cb+m]; }
    float gate = g_gate[bh];
    int s0 = c*TCH;
    for (int s = 0; s < TCH; s++) {
        size_t tok = (size_t)(b*S_ + s0 + s);
        float vt = g_qkv[tok*QS2_ + VOFF + h*DK_ + t];
        float num = 0.f, den = 0.f;
        #pragma unroll
        for (int m = 0; m < M_; m++) {
            float kpv = kp_s[s][m]; kv[m] += kpv*vt; kc[m] += kpv;
            float qpv = qp_s[s][m]; num += qpv*kv[m]; den += qpv*kc[m];
        }
        float o = num / (den + EPSF) * gate;
        size_t oi = tok*D_ + h*DK_ + t;
        __nv_bfloat16 hh = __float2bfloat16(o);
        g_ah[oi] = hh;
        g_al[oi] = __float2bfloat16(o - __bfloat162float(hh));
    }
}

// =============================================================================
extern "C" void kernel_launch(void* const* d_in, const int* in_sizes, int n_in,
                              void* d_out, int out_size)
{
    const int*   ids         = (const int*)  d_in[0];
    const int*   user_ids    = (const int*)  d_in[1];
    const float* id_embed    = (const float*)d_in[2];
    const float* feat_proj   = (const float*)d_in[3];
    const float* gamma       = (const float*)d_in[4];
    const float* gate_logits = (const float*)d_in[5];
    const float* wq          = (const float*)d_in[6];
    const float* wk          = (const float*)d_in[7];
    const float* wv          = (const float*)d_in[8];
    const float* wo          = (const float*)d_in[9];
    const float* omega       = (const float*)d_in[10];
    const float* ln1_a       = (const float*)d_in[11];
    const float* ln1_b       = (const float*)d_in[12];
    const float* ln2_a       = (const float*)d_in[13];
    const float* ln2_b       = (const float*)d_in[14];
    const float* ff_w1       = (const float*)d_in[15];
    const float* ff_b1       = (const float*)d_in[16];
    const float* ff_w2       = (const float*)d_in[17];
    const float* ff_b2       = (const float*)d_in[18];
    const float* fin_a       = (const float*)d_in[19];
    const float* fin_b       = (const float*)d_in[20];
    const float* proj_w      = (const float*)d_in[21];
    const float* proj_b      = (const float*)d_in[22];
    const float* feat_tbl    = (const float*)d_in[23];
    /* d_in[24] = prod_mask (derived as ids>=10) */
    const float* pe          = (const float*)d_in[25];
    float* out = (float*)d_out;

    float *px, *pqkv;
    __nv_bfloat16 *pxh, *pxl, *pah, *pal, *ph1h, *ph1l, *pwh, *pwl;
    cudaGetSymbolAddress((void**)&px,   g_x);
    cudaGetSymbolAddress((void**)&pxh,  g_xh);
    cudaGetSymbolAddress((void**)&pxl,  g_xl);
    cudaGetSymbolAddress((void**)&pqkv, g_qkv);
    cudaGetSymbolAddress((void**)&pah,  g_ah);
    cudaGetSymbolAddress((void**)&pal,  g_al);
    cudaGetSymbolAddress((void**)&ph1h, g_h1h);
    cudaGetSymbolAddress((void**)&ph1l, g_h1l);
    cudaGetSymbolAddress((void**)&pwh,  g_wh);
    cudaGetSymbolAddress((void**)&pwl,  g_wl);

    bool deep = true;
    deep &= (cudaFuncSetAttribute(tgemm4<0>, cudaFuncAttributeMaxDynamicSharedMemorySize, TG4_SMEM) == cudaSuccess);
    deep &= (cudaFuncSetAttribute(tgemm4<2>, cudaFuncAttributeMaxDynamicSharedMemorySize, TG4_SMEM) == cudaSuccess);
    deep &= (cudaFuncSetAttribute(tgemm4<3>, cudaFuncAttributeMaxDynamicSharedMemorySize, TG4_SMEM) == cudaSuccess);
    deep &= (cudaFuncSetAttribute(tgemm4<4>, cudaFuncAttributeMaxDynamicSharedMemorySize, TG4_SMEM) == cudaSuccess);
    deep &= (cudaGetLastError() == cudaSuccess);

    dim3 gFoldAll(D_/128, H_, 2*L_);
    dim3 gQKV(QS2_/128, BS_/128);    // (12, 32)
    dim3 gDD (D_/128,   BS_/128);    // (8, 32)
    dim3 gDF (DFF_/128, BS_/128);    // (32, 32)
    dim3 gVT (1, 32);
    dim3 gPfx(B_*H_, M_+1);          // (32, 17)

    const int GB_V    = (int)((DD_/8 + 255)/256);
    dim3 gVsplit(GB_V, L_);
    const int GB_WO   = (int)((4*DD_/8 + 255)/256);
    const int GB_FF   = (int)((16*DD_/8 + 255)/256);
    const int GB_PROJ = (int)(((size_t)VT_*D_/8 + 255)/256);

    #define RUN_TG(E, GRID, AH, AL, BH, BL, BI, RS, CF, CH, CL, NC, KK)            \
        do {                                                                        \
            if (deep) tgemm4<E><<<GRID, 256, TG4_SMEM>>>(AH, AL, BH, BL, BI, RS,    \
                                                         CF, CH, CL, NC, KK);       \
            else      tgemm2<E><<<GRID, 256>>>(AH, AL, BH, BL, BI, RS,              \
                                               CF, CH, CL, NC, KK);                 \
        } while (0)

    embtbl_kernel<<<VS_, 256>>>(id_embed, feat_proj, gamma, feat_tbl);
    xinit_kernel<<<(BS_*D_ + 255)/256, 256>>>(ids, pe);
    featfold_kernel<<<gFoldAll, 256>>>(wq, wk, omega);
    wsplitv_kernel<<<gVsplit, 256>>>((const float4*)wv);
    ln_kernel<<<BS_, 256>>>(px, ln1_a, ln1_b, pxh, pxl);
    RUN_TG(0, gQKV, pxh, pxl, pwh + OFF_QKV, pwl + OFF_QKV,
           (const float*)nullptr, (const float*)nullptr,
           pqkv, (__nv_bfloat16*)nullptr, (__nv_bfloat16*)nullptr, QS2_, D_);

    gate_kernel<<<B_, 32>>>(user_ids, gate_logits);
    wsplit_kernel<<<GB_WO,   256>>>((const float4*)wo,     (size_t)4*DD_/8,  OFF_WO);
    wsplit_kernel<<<GB_FF,   256>>>((const float4*)ff_w1,  (size_t)16*DD_/8, OFF_FF1);
    wsplit_kernel<<<GB_FF,   256>>>((const float4*)ff_w2,  (size_t)16*DD_/8, OFF_FF2);
    wsplit_kernel<<<GB_PROJ, 256>>>((const float4*)proj_w, (size_t)VT_*D_/8, OFF_PROJ);

    for (int l = 0; l < L_; l++) {
        if (l > 0) {
            ln_kernel<<<BS_, 256>>>(px, ln1_a + l*D_, ln1_b + l*D_, pxh, pxl);
            RUN_TG(0, gQKV, pxh, pxl,
                   pwh + OFF_QKV + (size_t)l*R_QKV, pwl + OFF_QKV + (size_t)l*R_QKV,
                   (const float*)nullptr, (const float*)nullptr,
                   pqkv, (__nv_bfloat16*)nullptr, (__nv_bfloat16*)nullptr, QS2_, D_);
        }
        perf_pass1<<<B_*H_*CCH, 64>>>();
        perf_prefix<<<gPfx, 64>>>();
        perf_pass2<<<B_*H_*CCH, 64>>>();
        RUN_TG(3, gDD, pah, pal,
               pwh + OFF_WO + (size_t)l*DD_, pwl + OFF_WO + (size_t)l*DD_,
               (const float*)nullptr, px,
               px, (__nv_bfloat16*)nullptr, (__nv_bfloat16*)nullptr, D_, D_);
        ln_kernel<<<BS_, 256>>>(px, ln2_a + l*D_, ln2_b + l*D_, pxh, pxl);
        RUN_TG(2, gDF, pxh, pxl,
               pwh + OFF_FF1 + (size_t)l*4*DD_, pwl + OFF_FF1 + (size_t)l*4*DD_,
               ff_b1 + (size_t)l*DFF_, (const float*)nullptr,
               (float*)nullptr, ph1h, ph1l, DFF_, D_);
        RUN_TG(4, gDD, ph1h, ph1l,
               pwh + OFF_FF2 + (size_t)l*4*DD_, pwl + OFF_FF2 + (size_t)l*4*DD_,
               ff_b2 + (size_t)l*D_, px,
               px, (__nv_bfloat16*)nullptr, (__nv_bfloat16*)nullptr, D_, DFF_);
    }

    ln_kernel<<<BS_, 256>>>(px, fin_a, fin_b, pxh, pxl);
    bgemm_proj<<<gVT, 256>>>(pxh, pxl, pwh + OFF_PROJ, pwl + OFF_PROJ,
                             proj_b, out, VT_, D_);
}